// round 17
// baseline (speedup 1.0000x reference)
#include <cuda_runtime.h>
#include <cuda_bf16.h>
#include <stdint.h>
#include <math.h>

#define Bb 8
#define Nn 2048
#define Dd 512
#define Pp 16
#define PH 512
#define ROWS (Bb*Nn)   // 16384
#define ESHIFT 40.0f
#define LOG2E 1.44269504f

// ---------------- scratch ---------------------------------------------------
__device__ __nv_bfloat16 g_ctx_h[(size_t)ROWS * Dd];
__device__ __nv_bfloat16 g_ctx_l[(size_t)ROWS * Dd];
__device__ __nv_bfloat16 g_W_h[(size_t)PH * Dd];
__device__ __nv_bfloat16 g_W_l[(size_t)PH * Dd];
__device__ __nv_bfloat16 g_G_h[(size_t)ROWS * PH];
__device__ __nv_bfloat16 g_G_l[(size_t)ROWS * PH];
__device__ float g_sum[ROWS];      // per-row (== per-col) sum of E
__device__ int   g_ready[128];     // G row-block counters (4 = ready)
__device__ int   g_sumready[128];  // per (z,block) sum contributions (16 = final)

// ---------------- small PTX helpers (base-ISA only) ------------------------
__device__ __forceinline__ uint32_t smem_u32(const void* p) {
    uint32_t a;
    asm("{ .reg .u64 t; cvta.to.shared.u64 t, %1; cvt.u32.u64 %0, t; }" : "=r"(a) : "l"(p));
    return a;
}
__device__ __forceinline__ void cpa16(uint32_t saddr, const void* g) {
    asm volatile("cp.async.cg.shared.global [%0], [%1], 16;" :: "r"(saddr), "l"(g));
}
#define CP_COMMIT() asm volatile("cp.async.commit_group;" ::: "memory")
#define CP_WAIT(n)  asm volatile("cp.async.wait_group %0;" :: "n"(n) : "memory")

__device__ __forceinline__ void ldsm4(uint32_t& d0, uint32_t& d1, uint32_t& d2, uint32_t& d3,
                                      uint32_t addr) {
    asm volatile("ldmatrix.sync.aligned.m8n8.x4.shared.b16 {%0,%1,%2,%3}, [%4];"
                 : "=r"(d0), "=r"(d1), "=r"(d2), "=r"(d3) : "r"(addr));
}
__device__ __forceinline__ void mma_bf16(float* c, const uint32_t* a, uint32_t b0, uint32_t b1) {
    asm volatile("mma.sync.aligned.m16n8k16.row.col.f32.bf16.bf16.f32 "
                 "{%0,%1,%2,%3}, {%4,%5,%6,%7}, {%8,%9}, {%0,%1,%2,%3};"
                 : "+f"(c[0]), "+f"(c[1]), "+f"(c[2]), "+f"(c[3])
                 : "r"(a[0]), "r"(a[1]), "r"(a[2]), "r"(a[3]), "r"(b0), "r"(b1));
}

// ---------------- fused split (ctx + W) + flag zeroing ----------------------
#define CTX_BLKS 8192      // 16384*512/4 float4 / 256
#define W_BLKS   256       // 512*512/4 float4 / 256
__global__ __launch_bounds__(256)
void split_all_kernel(const float* __restrict__ ctx, const float* __restrict__ W,
                      __nv_bfloat16* __restrict__ Ch, __nv_bfloat16* __restrict__ Cl,
                      __nv_bfloat16* __restrict__ Wh, __nv_bfloat16* __restrict__ Wl)
{
    const float* x; __nv_bfloat16 *h, *l; int i;
    if (blockIdx.x < CTX_BLKS) {
        i = blockIdx.x * 256 + threadIdx.x;
        if (i < ROWS) g_sum[i] = 0.f;
        if (i < 128)  { g_ready[i] = 0; g_sumready[i] = 0; }
        x = ctx; h = Ch; l = Cl;
    } else {
        i = (blockIdx.x - CTX_BLKS) * 256 + threadIdx.x;
        x = W; h = Wh; l = Wl;
    }
    float4 v = ((const float4*)x)[i];
    __nv_bfloat16 h0 = __float2bfloat16(v.x), h1 = __float2bfloat16(v.y);
    __nv_bfloat16 h2 = __float2bfloat16(v.z), h3 = __float2bfloat16(v.w);
    __nv_bfloat16 l0 = __float2bfloat16(v.x - __bfloat162float(h0));
    __nv_bfloat16 l1 = __float2bfloat16(v.y - __bfloat162float(h1));
    __nv_bfloat16 l2 = __float2bfloat16(v.z - __bfloat162float(h2));
    __nv_bfloat16 l3 = __float2bfloat16(v.w - __bfloat162float(h3));
    __nv_bfloat162 hp0 = __halves2bfloat162(h0, h1), hp1 = __halves2bfloat162(h2, h3);
    __nv_bfloat162 lp0 = __halves2bfloat162(l0, l1), lp1 = __halves2bfloat162(l2, l3);
    uint2 hv, lv;
    hv.x = *(uint32_t*)&hp0; hv.y = *(uint32_t*)&hp1;
    lv.x = *(uint32_t*)&lp0; lv.y = *(uint32_t*)&lp1;
    ((uint2*)h)[i] = hv;
    ((uint2*)l)[i] = lv;
}

// ---------------- persistent fused pipeline (K1 + K2 + NORM) ----------------
// Tiles: [0,512)      K1: G = relu(ctx@W^T), split-store, flags g_ready.
//        [512,1600)   K2: E = exp2(GG^T/16*log2e - s2), sums, flags g_sumready.
//        [1600,2688)  NORM: out = E/sum[col]*mask*mask + mirror to lower.
#define ROWB    144
#define NIT     24
#define MAT_B   18432
#define STAGE_B (2*MAT_B)
#define GEMM_SMEM (3*STAGE_B + 1024)
#define NTILES  2688
#define PGRID   296

__global__ __launch_bounds__(256, 2)
void fused_all(const __nv_bfloat16* __restrict__ ctxh, const __nv_bfloat16* __restrict__ ctxl,
               const __nv_bfloat16* __restrict__ Wh,   const __nv_bfloat16* __restrict__ Wl,
               __nv_bfloat16* __restrict__ Gh,         __nv_bfloat16* __restrict__ Gl,
               float* __restrict__ out,                const int* __restrict__ mask)
{
    extern __shared__ char dsm[];

    const int tid  = threadIdx.x;
    const int wid  = tid >> 5;
    const int lane = tid & 31;
    const int wm   = wid >> 2;
    const int wn   = wid & 3;

    const int r0 = tid >> 3;
    const int c0 = tid & 7;
    const uint32_t s_off0 = (uint32_t)r0 * ROWB + (uint32_t)c0 * 16;

    uint32_t as_b[3], bs_b[3];
#pragma unroll
    for (int s = 0; s < 3; s++) {
        as_b[s] = smem_u32(dsm + s * STAGE_B);
        bs_b[s] = smem_u32(dsm + s * STAGE_B + MAT_B);
    }

    const int rA = wm * 64 + (lane & 15);
    const int rB = wn * 32 + (lane & 15);
    const uint32_t half16 = (uint32_t)(lane >> 4) * 16;

    for (int T = blockIdx.x; T < NTILES; T += PGRID) {

        // ================= NORM tile =================
        if (T >= 1600) {
            const int T3 = T - 1600;
            const int z  = T3 / 136;
            int idx = T3 - z * 136, bi = 0, bj = 0, off = 0;
#pragma unroll 1
            for (int i = 0; i < 16; i++) {
                int cnt = 16 - i;
                if (idx < off + cnt) { bi = i; bj = i + idx - off; break; }
                off += cnt;
            }
            if (tid == 0) {
                volatile int* rf = g_sumready;
                while (rf[z * 16 + bi] < 16) { }
                while (rf[z * 16 + bj] < 16) { }
            }
            __syncthreads();
            __threadfence();

            float* smt = (float*)dsm;                 // [32][129]
            const size_t base = (size_t)z * Nn * Nn;
            const int zS = z * Nn;
            const int n0b = bj * 128;
            const int col4 = tid & 31;
            const int row0 = tid >> 5;

            float4 sum4 = __ldcg((const float4*)(g_sum + zS + n0b + col4 * 4));
            int4   mi4  = *(const int4*)(mask + zS + n0b + col4 * 4);
            float4 c4;
            c4.x = (1.0f / sum4.x) * (float)mi4.x;
            c4.y = (1.0f / sum4.y) * (float)mi4.y;
            c4.z = (1.0f / sum4.z) * (float)mi4.z;
            c4.w = (1.0f / sum4.w) * (float)mi4.w;

            const int col4t = tid & 7;
            const int rbase = tid >> 3;

#pragma unroll 1
            for (int strip = 0; strip < 4; strip++) {
                const int m0s = bi * 128 + strip * 32;
#pragma unroll
                for (int q = 0; q < 4; q++) {
                    const int row = row0 + 8 * q;
                    const size_t go = base + (size_t)(m0s + row) * Nn + n0b + col4 * 4;
                    float4 ev = __ldcg((const float4*)(out + go));
                    smt[row * 129 + col4 * 4 + 0] = ev.x;
                    smt[row * 129 + col4 * 4 + 1] = ev.y;
                    smt[row * 129 + col4 * 4 + 2] = ev.z;
                    smt[row * 129 + col4 * 4 + 3] = ev.w;
                    const float mr = (float)mask[zS + m0s + row];
                    float4 o;
                    o.x = ev.x * c4.x * mr; o.y = ev.y * c4.y * mr;
                    o.z = ev.z * c4.z * mr; o.w = ev.w * c4.w * mr;
                    *(float4*)(out + go) = o;
                }
                if (bi != bj) {
                    __syncthreads();
                    float4 sum4b = __ldcg((const float4*)(g_sum + zS + m0s + col4t * 4));
                    int4   mi4b  = *(const int4*)(mask + zS + m0s + col4t * 4);
                    float4 c4b;
                    c4b.x = (1.0f / sum4b.x) * (float)mi4b.x;
                    c4b.y = (1.0f / sum4b.y) * (float)mi4b.y;
                    c4b.z = (1.0f / sum4b.z) * (float)mi4b.z;
                    c4b.w = (1.0f / sum4b.w) * (float)mi4b.w;
#pragma unroll
                    for (int q = 0; q < 4; q++) {
                        const int rw = rbase + 32 * q;
                        float4 v;
                        v.x = smt[(col4t * 4 + 0) * 129 + rw];
                        v.y = smt[(col4t * 4 + 1) * 129 + rw];
                        v.z = smt[(col4t * 4 + 2) * 129 + rw];
                        v.w = smt[(col4t * 4 + 3) * 129 + rw];
                        const float mr = (float)mask[zS + n0b + rw];
                        float4 o;
                        o.x = v.x * c4b.x * mr; o.y = v.y * c4b.y * mr;
                        o.z = v.z * c4b.z * mr; o.w = v.w * c4b.w * mr;
                        *(float4*)(out + base + (size_t)(n0b + rw) * Nn + m0s + col4t * 4) = o;
                    }
                }
                __syncthreads();   // smem reuse across strips
            }
            continue;
        }

        // ================= GEMM tile (K1 or K2) =================
        const char *Ahb, *Alb, *Bhb, *Blb;
        int epi, m0, n0, z = 0, yrow = 0;
        if (T < 512) {
            epi  = 1;
            yrow = T >> 2;
            m0 = yrow * 128;
            n0 = (T & 3) * 128;
            Ahb = (const char*)ctxh; Alb = (const char*)ctxl;
            Bhb = (const char*)Wh;   Blb = (const char*)Wl;
        } else {
            epi = 0;
            int T2 = T - 512;
            z = T2 / 136;
            int idx = T2 - z * 136, bi = 0, bj = 0, off = 0;
#pragma unroll 1
            for (int i = 0; i < 16; i++) {
                int cnt = 16 - i;
                if (idx < off + cnt) { bi = i; bj = i + idx - off; break; }
                off += cnt;
            }
            m0 = bi * 128; n0 = bj * 128;
            const char* Gb = (const char*)(Gh + (size_t)z * Nn * PH);
            const char* Gc = (const char*)(Gl + (size_t)z * Nn * PH);
            Ahb = Gb; Alb = Gc; Bhb = Gb; Blb = Gc;
            if (tid == 0) {
                volatile int* rf = g_ready;
                while (rf[z * 16 + bi] < 4) { }
                while (rf[z * 16 + bj] < 4) { }
            }
            __syncthreads();
            __threadfence();
        }

        const size_t a_off0 = (size_t)(m0 + r0) * 1024 + (size_t)c0 * 16;
        const size_t b_off0 = (size_t)(n0 + r0) * 1024 + (size_t)c0 * 16;

        float acc[4][4][4];
#pragma unroll
        for (int i = 0; i < 4; i++)
#pragma unroll
            for (int j = 0; j < 4; j++)
#pragma unroll
                for (int k = 0; k < 4; k++) acc[i][j][k] = 0.f;

        auto prefetch = [&](int it, int buf) {
            const int term = it >> 3;
            const int kc   = it & 7;
            const char* Ab  = (term == 2) ? Alb : Ahb;
            const char* Bbp = (term == 1) ? Blb : Bhb;
            const size_t koff = (size_t)kc * 128;
            uint32_t sa = as_b[buf] + s_off0;
            uint32_t sb = bs_b[buf] + s_off0;
#pragma unroll
            for (int q = 0; q < 4; q++) {
                cpa16(sa + q * 32 * ROWB, Ab  + a_off0 + (size_t)(q * 32) * 1024 + koff);
                cpa16(sb + q * 32 * ROWB, Bbp + b_off0 + (size_t)(q * 32) * 1024 + koff);
            }
        };

        prefetch(0, 0); CP_COMMIT();
        prefetch(1, 1); CP_COMMIT();

#pragma unroll 6
        for (int it = 0; it < NIT; ++it) {
            const int buf = it % 3;
            if (it < NIT - 1) { CP_WAIT(1); } else { CP_WAIT(0); }
            __syncthreads();

#pragma unroll
            for (int ks = 0; ks < 4; ks++) {
                uint32_t a[4][4];
                uint32_t b[2][4];
#pragma unroll
                for (int mi = 0; mi < 4; mi++) {
                    uint32_t addr = as_b[buf] + (uint32_t)(rA + mi * 16) * ROWB
                                  + (uint32_t)ks * 32 + half16;
                    ldsm4(a[mi][0], a[mi][1], a[mi][2], a[mi][3], addr);
                }
#pragma unroll
                for (int nb = 0; nb < 2; nb++) {
                    uint32_t addr = bs_b[buf] + (uint32_t)(rB + nb * 16) * ROWB
                                  + (uint32_t)ks * 32 + half16;
                    ldsm4(b[nb][0], b[nb][1], b[nb][2], b[nb][3], addr);
                }
#pragma unroll
                for (int mi = 0; mi < 4; mi++)
#pragma unroll
                    for (int g = 0; g < 4; g++)
                        mma_bf16(acc[mi][g], a[mi], b[g >> 1][g & 1], b[g >> 1][(g & 1) + 2]);
            }
            if (it + 2 < NIT) { prefetch(it + 2, (it + 2) % 3); CP_COMMIT(); }
        }

        const int er = m0 + wm * 64 + (lane >> 2);
        const int ec = n0 + wn * 32 + (lane & 3) * 2;

        if (epi == 1) {
#pragma unroll
            for (int mi = 0; mi < 4; mi++)
#pragma unroll
                for (int g = 0; g < 4; g++) {
                    const int r = er + mi * 16;
                    const int c = ec + g * 8;
#pragma unroll
                    for (int hrow = 0; hrow < 2; hrow++) {
                        float v0 = fmaxf(acc[mi][g][2 * hrow + 0], 0.f);
                        float v1 = fmaxf(acc[mi][g][2 * hrow + 1], 0.f);
                        __nv_bfloat16 h0 = __float2bfloat16(v0), h1 = __float2bfloat16(v1);
                        __nv_bfloat16 l0 = __float2bfloat16(v0 - __bfloat162float(h0));
                        __nv_bfloat16 l1 = __float2bfloat16(v1 - __bfloat162float(h1));
                        __nv_bfloat162 hp = __halves2bfloat162(h0, h1);
                        __nv_bfloat162 lp = __halves2bfloat162(l0, l1);
                        const size_t o = (size_t)(r + 8 * hrow) * PH + c;
                        *(uint32_t*)(Gh + o) = *(uint32_t*)&hp;
                        *(uint32_t*)(Gl + o) = *(uint32_t*)&lp;
                    }
                }
            __threadfence();
            __syncthreads();
            if (tid == 0) atomicAdd(&g_ready[yrow], 1);
        } else {
            const float a2 = (1.0f / (float)Pp) * LOG2E;
            const float s2 = ESHIFT * LOG2E;
            const size_t zC = (size_t)z * Nn * Nn;
#pragma unroll
            for (int mi = 0; mi < 4; mi++)
#pragma unroll
                for (int g = 0; g < 4; g++)
#pragma unroll
                    for (int k = 0; k < 4; k++)
                        acc[mi][g][k] = exp2f(fmaf(acc[mi][g][k], a2, -s2));

#pragma unroll
            for (int mi = 0; mi < 4; mi++)
#pragma unroll
                for (int g = 0; g < 4; g++) {
                    const int r = er + mi * 16;
                    const int c = ec + g * 8;
                    *(float2*)(out + zC + (size_t)r * Nn + c)       = make_float2(acc[mi][g][0], acc[mi][g][1]);
                    *(float2*)(out + zC + (size_t)(r + 8) * Nn + c) = make_float2(acc[mi][g][2], acc[mi][g][3]);
                }

            float* srow = (float*)(dsm + 3 * STAGE_B);   // [128]
            float* scol = srow + 128;                    // [128]
            __syncthreads();
            if (tid < 128) { srow[tid] = 0.f; scol[tid] = 0.f; }
            __syncthreads();

#pragma unroll
            for (int mi = 0; mi < 4; mi++)
#pragma unroll
                for (int h = 0; h < 2; h++) {
                    float rp = 0.f;
#pragma unroll
                    for (int g = 0; g < 4; g++)
                        rp += acc[mi][g][2 * h + 0] + acc[mi][g][2 * h + 1];
                    rp += __shfl_xor_sync(0xffffffffu, rp, 1);
                    rp += __shfl_xor_sync(0xffffffffu, rp, 2);
                    if ((lane & 3) == 0) {
                        int wr = wm * 64 + (lane >> 2) + mi * 16 + 8 * h;
                        atomicAdd(&srow[wr], rp);
                    }
                }
#pragma unroll
            for (int g = 0; g < 4; g++)
#pragma unroll
                for (int p = 0; p < 2; p++) {
                    float cp = 0.f;
#pragma unroll
                    for (int mi = 0; mi < 4; mi++)
                        cp += acc[mi][g][p] + acc[mi][g][2 + p];
                    cp += __shfl_xor_sync(0xffffffffu, cp, 4);
                    cp += __shfl_xor_sync(0xffffffffu, cp, 8);
                    cp += __shfl_xor_sync(0xffffffffu, cp, 16);
                    if (lane < 4) {
                        int wc = wn * 32 + (lane & 3) * 2 + 8 * g + p;
                        atomicAdd(&scol[wc], cp);
                    }
                }
            __syncthreads();
            const size_t zS = (size_t)z * Nn;
            if (tid < 128) {
                atomicAdd(&g_sum[zS + m0 + tid], srow[tid]);
                if (m0 != n0) atomicAdd(&g_sum[zS + n0 + tid], scol[tid]);
            }
            __threadfence();
            __syncthreads();
            if (tid == 0) {
                atomicAdd(&g_sumready[z * 16 + (m0 >> 7)], 1);
                if (m0 != n0) atomicAdd(&g_sumready[z * 16 + (n0 >> 7)], 1);
            }
        }
    }
}

// ---------------- launch ---------------------------------------------------
extern "C" void kernel_launch(void* const* d_in, const int* in_sizes, int n_in,
                              void* d_out, int out_size)
{
    const float* ctx  = (const float*)d_in[0];   // [8, 2048, 512]
    const float* W    = (const float*)d_in[1];   // [16, 32, 512]
    const int*   mask = (const int*)d_in[2];     // [8, 2048]
    float* out = (float*)d_out;                  // [8, 2048, 2048]

    void *p_ch, *p_cl, *p_wh, *p_wl, *p_gh, *p_gl;
    cudaGetSymbolAddress(&p_ch, g_ctx_h); cudaGetSymbolAddress(&p_cl, g_ctx_l);
    cudaGetSymbolAddress(&p_wh, g_W_h);   cudaGetSymbolAddress(&p_wl, g_W_l);
    cudaGetSymbolAddress(&p_gh, g_G_h);   cudaGetSymbolAddress(&p_gl, g_G_l);
    __nv_bfloat16* Ch = (__nv_bfloat16*)p_ch; __nv_bfloat16* Cl = (__nv_bfloat16*)p_cl;
    __nv_bfloat16* Wh = (__nv_bfloat16*)p_wh; __nv_bfloat16* Wl = (__nv_bfloat16*)p_wl;
    __nv_bfloat16* Gh = (__nv_bfloat16*)p_gh; __nv_bfloat16* Gl = (__nv_bfloat16*)p_gl;

    cudaFuncSetAttribute(fused_all, cudaFuncAttributeMaxDynamicSharedMemorySize, GEMM_SMEM);

    // K0: fused splits (ctx + W) + flag zeroing
    split_all_kernel<<<CTX_BLKS + W_BLKS, 256>>>(ctx, W, Ch, Cl, Wh, Wl);
    // K1+K2+NORM persistent pipeline
    fused_all<<<PGRID, 256, GEMM_SMEM>>>(Ch, Cl, Wh, Wl, Gh, Gl, out, mask);
}